// round 2
// baseline (speedup 1.0000x reference)
#include <cuda_runtime.h>

#define N_PT   400000
#define N_SC   1000000
#define M_SEG  100000
#define SH_    120
#define MAPSZ  (4*SH_*SH_*SH_)   /* 6,912,000 */
#define BN_EPS 1e-5f

// ---------------- scratch (static __device__, no allocations) ----------------
__device__ int   d_map[MAPSZ];
__device__ int   d_inv[N_PT];
__device__ int   d_cnt[N_PT];
__device__ float d_dsum[(size_t)N_PT*64];
__device__ float d_h   [(size_t)N_PT*64];
__device__ float d_tpre[(size_t)N_PT*64];
__device__ float d_usum[(size_t)M_SEG*64];
__device__ int   d_ucnt[M_SEG];

__device__ __forceinline__ float lrelu(float x){ return x >= 0.f ? x : 0.1f*x; }

// ---------------- K1: voxel-key claim + inverse map + counts ----------------
__global__ void k_claim(const int4* __restrict__ coors){
    int i = blockIdx.x*blockDim.x + threadIdx.x;
    if (i >= N_PT) return;
    int4 c = coors[i];
    int key = ((c.x*SH_ + (c.y>>1))*SH_ + (c.z>>1))*SH_ + (c.w>>1);
    int old = atomicCAS(&d_map[key], -1, i);     // first claimer becomes rep; value is final once set
    int rep = (old == -1) ? i : old;
    d_inv[i] = rep;
    atomicAdd(&d_cnt[rep], 1);
}

// ---------------- K2: accumulate feature sums per representative ----------------
__global__ void k_accum(const float* __restrict__ feat){
    int idx = blockIdx.x*blockDim.x + threadIdx.x;
    if (idx >= N_PT*64) return;
    int i = idx >> 6;
    atomicAdd(&d_dsum[d_inv[i]*64 + (idx & 63)], feat[idx]);
}

// ---------------- K3: rep-row MLP 64->32->32->64 with BN, fused, tiled ----------------
// block = 64 rows, 256 threads; dynamic smem 53760 B
__global__ void k_mlp(
    const float* __restrict__ W1, const float* __restrict__ b1,
    const float* __restrict__ g1, const float* __restrict__ be1,
    const float* __restrict__ m1, const float* __restrict__ v1,
    const float* __restrict__ W2, const float* __restrict__ b2,
    const float* __restrict__ g2, const float* __restrict__ be2,
    const float* __restrict__ m2, const float* __restrict__ v2,
    const float* __restrict__ W3, const float* __restrict__ b3)
{
    extern __shared__ float sm[];
    float* sW1 = sm;               // [64][32]
    float* sW2 = sW1 + 64*32;      // [32][32]
    float* sW3 = sW2 + 32*32;      // [32][64]
    float* sA  = sW3 + 32*64;      // [64][65]  act^T  (k-major, row stride 65 -> conflict-free staging)
    float* sH1 = sA  + 64*65;      // [32][65]
    float* sH2 = sH1 + 32*65;      // [32][65]
    int tid = threadIdx.x;

    for (int i = tid; i < 64*32; i += 256) sW1[i] = W1[i];
    for (int i = tid; i < 32*32; i += 256) sW2[i] = W2[i];
    for (int i = tid; i < 32*64; i += 256) sW3[i] = W3[i];

    int r0 = blockIdx.x * 64;
    for (int idx = tid; idx < 4096; idx += 256) {
        int row = idx >> 6, k = idx & 63;
        int cc = d_cnt[r0 + row];
        float sc = (cc > 1) ? (1.f/(float)cc) : 1.f;
        sA[k*65 + row] = d_dsum[r0*64 + idx] * sc;
    }
    __syncthreads();

    int tx = tid & 15, ty = tid >> 4;
    int c2 = 2*tx, r4 = 4*ty;

    // ---- GEMM1: [64r x 64k] @ [64k x 32c] ----
    float a00=0,a01=0,a10=0,a11=0,a20=0,a21=0,a30=0,a31=0;
    #pragma unroll 8
    for (int k = 0; k < 64; ++k) {
        float2 w = *(const float2*)&sW1[k*32 + c2];
        float x0 = sA[k*65+r4+0], x1 = sA[k*65+r4+1], x2 = sA[k*65+r4+2], x3 = sA[k*65+r4+3];
        a00 += x0*w.x; a01 += x0*w.y;
        a10 += x1*w.x; a11 += x1*w.y;
        a20 += x2*w.x; a21 += x2*w.y;
        a30 += x3*w.x; a31 += x3*w.y;
    }
    {
        float bb0=b1[c2], bb1=b1[c2+1];
        float s0=g1[c2]*rsqrtf(v1[c2]+BN_EPS), s1=g1[c2+1]*rsqrtf(v1[c2+1]+BN_EPS);
        float mm0=m1[c2], mm1=m1[c2+1], q0=be1[c2], q1=be1[c2+1];
        sH1[c2*65+r4+0]     = (lrelu(a00+bb0)-mm0)*s0+q0;
        sH1[c2*65+r4+1]     = (lrelu(a10+bb0)-mm0)*s0+q0;
        sH1[c2*65+r4+2]     = (lrelu(a20+bb0)-mm0)*s0+q0;
        sH1[c2*65+r4+3]     = (lrelu(a30+bb0)-mm0)*s0+q0;
        sH1[(c2+1)*65+r4+0] = (lrelu(a01+bb1)-mm1)*s1+q1;
        sH1[(c2+1)*65+r4+1] = (lrelu(a11+bb1)-mm1)*s1+q1;
        sH1[(c2+1)*65+r4+2] = (lrelu(a21+bb1)-mm1)*s1+q1;
        sH1[(c2+1)*65+r4+3] = (lrelu(a31+bb1)-mm1)*s1+q1;
    }
    __syncthreads();

    // ---- GEMM2: [64r x 32k] @ [32k x 32c] ----
    a00=0;a01=0;a10=0;a11=0;a20=0;a21=0;a30=0;a31=0;
    #pragma unroll 8
    for (int k = 0; k < 32; ++k) {
        float2 w = *(const float2*)&sW2[k*32 + c2];
        float x0 = sH1[k*65+r4+0], x1 = sH1[k*65+r4+1], x2 = sH1[k*65+r4+2], x3 = sH1[k*65+r4+3];
        a00 += x0*w.x; a01 += x0*w.y;
        a10 += x1*w.x; a11 += x1*w.y;
        a20 += x2*w.x; a21 += x2*w.y;
        a30 += x3*w.x; a31 += x3*w.y;
    }
    {
        float bb0=b2[c2], bb1=b2[c2+1];
        float s0=g2[c2]*rsqrtf(v2[c2]+BN_EPS), s1=g2[c2+1]*rsqrtf(v2[c2+1]+BN_EPS);
        float mm0=m2[c2], mm1=m2[c2+1], q0=be2[c2], q1=be2[c2+1];
        sH2[c2*65+r4+0]     = (lrelu(a00+bb0)-mm0)*s0+q0;
        sH2[c2*65+r4+1]     = (lrelu(a10+bb0)-mm0)*s0+q0;
        sH2[c2*65+r4+2]     = (lrelu(a20+bb0)-mm0)*s0+q0;
        sH2[c2*65+r4+3]     = (lrelu(a30+bb0)-mm0)*s0+q0;
        sH2[(c2+1)*65+r4+0] = (lrelu(a01+bb1)-mm1)*s1+q1;
        sH2[(c2+1)*65+r4+1] = (lrelu(a11+bb1)-mm1)*s1+q1;
        sH2[(c2+1)*65+r4+2] = (lrelu(a21+bb1)-mm1)*s1+q1;
        sH2[(c2+1)*65+r4+3] = (lrelu(a31+bb1)-mm1)*s1+q1;
    }
    __syncthreads();

    // ---- GEMM3: [64r x 32k] @ [32k x 64c] ----
    int c4 = 4*tx;
    float acc[4][4] = {};
    #pragma unroll 8
    for (int k = 0; k < 32; ++k) {
        float4 w = *(const float4*)&sW3[k*64 + c4];
        #pragma unroll
        for (int i = 0; i < 4; ++i) {
            float x = sH2[k*65 + r4 + i];
            acc[i][0] += x*w.x; acc[i][1] += x*w.y; acc[i][2] += x*w.z; acc[i][3] += x*w.w;
        }
    }
    {
        float bb0=b3[c4], bb1=b3[c4+1], bb2=b3[c4+2], bb3=b3[c4+3];
        #pragma unroll
        for (int i = 0; i < 4; ++i) {
            float4 o;
            o.x = lrelu(acc[i][0]+bb0);
            o.y = lrelu(acc[i][1]+bb1);
            o.z = lrelu(acc[i][2]+bb2);
            o.w = lrelu(acc[i][3]+bb3);
            *(float4*)&d_h[(size_t)(r0+r4+i)*64 + c4] = o;
        }
    }
}

// ---------------- K4: t_pre = [lrelu(feat@Win+bin), h[inv]] @ Wo1 + bo1 ----------------
// block = 64 points, 256 threads; dynamic smem 99328 B
__global__ void k_tpre(const float* __restrict__ feat,
                       const float* __restrict__ Win, const float* __restrict__ bin,
                       const float* __restrict__ Wo1, const float* __restrict__ bo1)
{
    extern __shared__ float sm[];
    float* sWin = sm;               // [64][64]
    float* sWo1 = sWin + 4096;      // [128][64]
    float* sA   = sWo1 + 8192;      // [64][65]  feat^T
    float* sC   = sA   + 4160;      // [128][65] cat^T (rows 0..63 id, 64..127 pp)
    int*   sInv = (int*)(sC + 8320);
    int tid = threadIdx.x;

    for (int i = tid; i < 4096; i += 256) sWin[i] = Win[i];
    for (int i = tid; i < 8192; i += 256) sWo1[i] = Wo1[i];
    int p0 = blockIdx.x * 64;
    if (tid < 64) sInv[tid] = d_inv[p0 + tid];
    for (int idx = tid; idx < 4096; idx += 256) {
        int row = idx >> 6, k = idx & 63;
        sA[k*65 + row] = feat[(size_t)p0*64 + idx];
    }
    __syncthreads();

    // stage pp (gather h rows) into cat rows 64..127
    for (int idx = tid; idx < 4096; idx += 256) {
        int row = idx >> 6, k = idx & 63;
        sC[(64+k)*65 + row] = d_h[(size_t)sInv[row]*64 + k];
    }

    int tx = tid & 15, ty = tid >> 4;
    int c4 = 4*tx, r4 = 4*ty;

    // ---- identity GEMM: 64x64x64 ----
    float acc[4][4] = {};
    #pragma unroll 8
    for (int k = 0; k < 64; ++k) {
        float4 w = *(const float4*)&sWin[k*64 + c4];
        #pragma unroll
        for (int i = 0; i < 4; ++i) {
            float x = sA[k*65 + r4 + i];
            acc[i][0] += x*w.x; acc[i][1] += x*w.y; acc[i][2] += x*w.z; acc[i][3] += x*w.w;
        }
    }
    {
        float bb0=bin[c4], bb1=bin[c4+1], bb2=bin[c4+2], bb3=bin[c4+3];
        #pragma unroll
        for (int i = 0; i < 4; ++i) {
            sC[(c4+0)*65 + r4+i] = lrelu(acc[i][0]+bb0);
            sC[(c4+1)*65 + r4+i] = lrelu(acc[i][1]+bb1);
            sC[(c4+2)*65 + r4+i] = lrelu(acc[i][2]+bb2);
            sC[(c4+3)*65 + r4+i] = lrelu(acc[i][3]+bb3);
        }
    }
    __syncthreads();

    // ---- t_pre GEMM: 64x128x64 ----
    float o[4][4] = {};
    #pragma unroll 8
    for (int k = 0; k < 128; ++k) {
        float4 w = *(const float4*)&sWo1[k*64 + c4];
        #pragma unroll
        for (int i = 0; i < 4; ++i) {
            float x = sC[k*65 + r4 + i];
            o[i][0] += x*w.x; o[i][1] += x*w.y; o[i][2] += x*w.z; o[i][3] += x*w.w;
        }
    }
    {
        float bb0=bo1[c4], bb1=bo1[c4+1], bb2=bo1[c4+2], bb3=bo1[c4+3];
        #pragma unroll
        for (int i = 0; i < 4; ++i) {
            float4 ov;
            ov.x = o[i][0]+bb0; ov.y = o[i][1]+bb1; ov.z = o[i][2]+bb2; ov.w = o[i][3]+bb3;
            *(float4*)&d_tpre[(size_t)(p0+r4+i)*64 + c4] = ov;
        }
    }
}

// ---------------- K5: gather + lrelu + segment accumulate ----------------
__global__ void k_scatter(const int* __restrict__ cinv, const int* __restrict__ sinv){
    int t = blockIdx.x*blockDim.x + threadIdx.x;
    if (t >= N_SC*16) return;
    int p = t >> 4, q = t & 15;
    int j = cinv[p];
    int m = sinv[p];
    float4 v = *(const float4*)&d_tpre[(size_t)j*64 + q*4];
    v.x = lrelu(v.x); v.y = lrelu(v.y); v.z = lrelu(v.z); v.w = lrelu(v.w);
    float* dst = &d_usum[(size_t)m*64 + q*4];
    atomicAdd(dst+0, v.x);
    atomicAdd(dst+1, v.y);
    atomicAdd(dst+2, v.z);
    atomicAdd(dst+3, v.w);
    if (q == 0) atomicAdd(&d_ucnt[m], 1);
}

// ---------------- K6: v_feat = (u_sum/cnt) @ Wo2 + bo2 (0 for empty segs) ----------------
__global__ void k_final(const float* __restrict__ Wo2, const float* __restrict__ bo2,
                        float* __restrict__ out)
{
    __shared__ float sW[64*64];
    __shared__ float sA[64*65];
    int tid = threadIdx.x;
    for (int i = tid; i < 4096; i += 256) sW[i] = Wo2[i];
    int m0 = blockIdx.x * 64;
    for (int idx = tid; idx < 4096; idx += 256) {
        int row = idx >> 6, k = idx & 63;
        int m = m0 + row;
        float v = 0.f;
        if (m < M_SEG) {
            int cc = d_ucnt[m];
            v = (cc > 0) ? d_usum[(size_t)m*64 + k] * (1.f/(float)cc) : 0.f;
        }
        sA[k*65 + row] = v;
    }
    __syncthreads();

    int tx = tid & 15, ty = tid >> 4;
    int c4 = 4*tx, r4 = 4*ty;
    float acc[4][4] = {};
    #pragma unroll 8
    for (int k = 0; k < 64; ++k) {
        float4 w = *(const float4*)&sW[k*64 + c4];
        #pragma unroll
        for (int i = 0; i < 4; ++i) {
            float x = sA[k*65 + r4 + i];
            acc[i][0] += x*w.x; acc[i][1] += x*w.y; acc[i][2] += x*w.z; acc[i][3] += x*w.w;
        }
    }
    float bb0=bo2[c4], bb1=bo2[c4+1], bb2=bo2[c4+2], bb3=bo2[c4+3];
    #pragma unroll
    for (int i = 0; i < 4; ++i) {
        int m = m0 + r4 + i;
        if (m < M_SEG) {
            int cc = d_ucnt[m];
            float4 ov;
            if (cc > 0) { ov.x = acc[i][0]+bb0; ov.y = acc[i][1]+bb1; ov.z = acc[i][2]+bb2; ov.w = acc[i][3]+bb3; }
            else        { ov.x = 0.f; ov.y = 0.f; ov.z = 0.f; ov.w = 0.f; }
            *(float4*)&out[(size_t)m*64 + c4] = ov;
        }
    }
}

// ---------------- launch ----------------
extern "C" void kernel_launch(void* const* d_in, const int* in_sizes, int n_in,
                              void* d_out, int out_size)
{
    const float* feat = (const float*)d_in[0];
    const int4*  coors = (const int4*)d_in[1];
    const int*   cinv  = (const int*)d_in[2];
    const int*   sinv  = (const int*)d_in[3];
    const float* Win = (const float*)d_in[4];
    const float* bin = (const float*)d_in[5];
    const float* W1  = (const float*)d_in[6];
    const float* b1  = (const float*)d_in[7];
    const float* g1  = (const float*)d_in[8];
    const float* be1 = (const float*)d_in[9];
    const float* m1  = (const float*)d_in[10];
    const float* v1  = (const float*)d_in[11];
    const float* W2  = (const float*)d_in[12];
    const float* b2  = (const float*)d_in[13];
    const float* g2  = (const float*)d_in[14];
    const float* be2 = (const float*)d_in[15];
    const float* m2  = (const float*)d_in[16];
    const float* v2  = (const float*)d_in[17];
    const float* W3  = (const float*)d_in[18];
    const float* b3  = (const float*)d_in[19];
    const float* Wo1 = (const float*)d_in[20];
    const float* bo1 = (const float*)d_in[21];
    const float* Wo2 = (const float*)d_in[22];
    const float* bo2 = (const float*)d_in[23];
    float* out = (float*)d_out;

    // raise dynamic smem caps (idempotent, no allocation)
    cudaFuncSetAttribute(k_mlp,  cudaFuncAttributeMaxDynamicSharedMemorySize, 53760);
    cudaFuncSetAttribute(k_tpre, cudaFuncAttributeMaxDynamicSharedMemorySize, 99328);

    void *p_map, *p_cnt, *p_dsum, *p_usum, *p_ucnt;
    cudaGetSymbolAddress(&p_map,  d_map);
    cudaGetSymbolAddress(&p_cnt,  d_cnt);
    cudaGetSymbolAddress(&p_dsum, d_dsum);
    cudaGetSymbolAddress(&p_usum, d_usum);
    cudaGetSymbolAddress(&p_ucnt, d_ucnt);
    cudaMemsetAsync(p_map,  0xFF, sizeof(int)  * MAPSZ);           // -1
    cudaMemsetAsync(p_cnt,  0,    sizeof(int)  * N_PT);
    cudaMemsetAsync(p_dsum, 0,    sizeof(float)* (size_t)N_PT*64);
    cudaMemsetAsync(p_usum, 0,    sizeof(float)* (size_t)M_SEG*64);
    cudaMemsetAsync(p_ucnt, 0,    sizeof(int)  * M_SEG);

    k_claim  <<<(N_PT + 255)/256, 256>>>(coors);
    k_accum  <<<(N_PT*64)/256, 256>>>(feat);
    k_mlp    <<<N_PT/64, 256, 53760>>>(W1,b1,g1,be1,m1,v1,W2,b2,g2,be2,m2,v2,W3,b3);
    k_tpre   <<<N_PT/64, 256, 99328>>>(feat, Win, bin, Wo1, bo1);
    k_scatter<<<(N_SC*16)/256, 256>>>(cinv, sinv);
    k_final  <<<(M_SEG + 63)/64, 256>>>(Wo2, bo2, out);
}

// round 3
// speedup vs baseline: 1.1662x; 1.1662x over previous
#include <cuda_runtime.h>

#define N_PT   400000
#define N_SC   1000000
#define M_SEG  100000
#define SH_    120
#define MAPSZ  (4*SH_*SH_*SH_)   /* 6,912,000 */
#define BN_EPS 1e-5f
#define PAD    68                /* activation tile row stride: 16B-aligned + few conflicts */

// ---------------- scratch (static __device__, no allocations) ----------------
__device__ int   d_map[MAPSZ];
__device__ int   d_inv[N_PT];
__device__ int   d_cnt[N_PT];
__device__ float d_dsum[(size_t)N_PT*64];
__device__ float d_h2  [(size_t)N_PT*64];   // h @ Wo1_bot  (rep rows)
__device__ float d_tpre[(size_t)N_PT*64];   // cat @ Wo1 + bo1 per unique point row
__device__ float d_usum[(size_t)M_SEG*64];
__device__ int   d_ucnt[M_SEG];

__device__ __forceinline__ float lrelu(float x){ return x >= 0.f ? x : 0.1f*x; }

__device__ __forceinline__ void red_v4(float* p, float4 v){
    asm volatile("red.global.add.v4.f32 [%0], {%1, %2, %3, %4};"
                 :: "l"(p), "f"(v.x), "f"(v.y), "f"(v.z), "f"(v.w) : "memory");
}

// ---------------- K1: voxel-key claim + inverse map + counts ----------------
__global__ void k_claim(const int4* __restrict__ coors){
    int i = blockIdx.x*blockDim.x + threadIdx.x;
    if (i >= N_PT) return;
    int4 c = coors[i];
    int key = ((c.x*SH_ + (c.y>>1))*SH_ + (c.z>>1))*SH_ + (c.w>>1);
    int old = atomicCAS(&d_map[key], -1, i);   // first claimer is rep; value final once set
    int rep = (old == -1) ? i : old;
    d_inv[i] = rep;
    atomicAdd(&d_cnt[rep], 1);
}

// ---------------- K2: sparse feature accumulate (only multi-member reps) ----------------
__global__ void k_accum(const float* __restrict__ feat){
    int i = blockIdx.x*blockDim.x + threadIdx.x;
    if (i >= N_PT) return;
    int rep = d_inv[i];
    if (__ldg(&d_cnt[rep]) > 1) {
        const float4* src = (const float4*)&feat[(size_t)i*64];
        float* dst = &d_dsum[(size_t)rep*64];
        #pragma unroll
        for (int q = 0; q < 16; ++q) red_v4(&dst[4*q], src[q]);
    }
}

// ---------------- K3: rep MLP 64->32->32->64 (+BN,+lrelu) then @Wo1_bot -> d_h2 ----------
// block = 64 rows, 256 threads; dynamic smem 89088 B
__global__ void __launch_bounds__(256) k_mlp(
    const float* __restrict__ feat,
    const float* __restrict__ W1, const float* __restrict__ b1,
    const float* __restrict__ g1, const float* __restrict__ be1,
    const float* __restrict__ m1, const float* __restrict__ v1,
    const float* __restrict__ W2, const float* __restrict__ b2,
    const float* __restrict__ g2, const float* __restrict__ be2,
    const float* __restrict__ m2, const float* __restrict__ v2,
    const float* __restrict__ W3, const float* __restrict__ b3,
    const float* __restrict__ Wo1)
{
    extern __shared__ float sm[];
    float* sW1 = sm;               // [64][32]
    float* sW2 = sW1 + 64*32;      // [32][32]
    float* sW3 = sW2 + 32*32;      // [32][64]
    float* sWb = sW3 + 32*64;      // [64][64] = Wo1 rows 64..127
    float* sA  = sWb + 64*64;      // [64][PAD] down^T
    float* sH1 = sA  + 64*PAD;     // [32][PAD]
    float* sH2 = sH1 + 32*PAD;     // [32][PAD]
    float* sH3 = sH2 + 32*PAD;     // [64][PAD] h^T
    int tid = threadIdx.x;

    for (int i = tid; i < 64*32; i += 256) sW1[i] = W1[i];
    for (int i = tid; i < 32*32; i += 256) sW2[i] = W2[i];
    for (int i = tid; i < 32*64; i += 256) sW3[i] = W3[i];
    for (int i = tid; i < 64*64; i += 256) sWb[i] = Wo1[64*64 + i];

    int r0 = blockIdx.x * 64;
    for (int idx = tid; idx < 4096; idx += 256) {
        int row = idx >> 6, k = idx & 63;
        int cc = d_cnt[r0 + row];
        float v = (cc > 1) ? d_dsum[(size_t)r0*64 + idx] * (1.f/(float)cc)
                           : feat[(size_t)r0*64 + idx];
        sA[k*PAD + row] = v;
    }
    __syncthreads();

    int tx = tid & 15, ty = tid >> 4;
    int c2 = 2*tx, r4 = 4*ty;

    // ---- GEMM1: [64r x 64k] @ [64k x 32c] + bias + lrelu + BN -> sH1 ----
    {
        float a0x=0,a0y=0,a1x=0,a1y=0,a2x=0,a2y=0,a3x=0,a3y=0;
        #pragma unroll 8
        for (int k = 0; k < 64; ++k) {
            float2 w = *(const float2*)&sW1[k*32 + c2];
            float4 x = *(const float4*)&sA[k*PAD + r4];
            a0x += x.x*w.x; a0y += x.x*w.y;
            a1x += x.y*w.x; a1y += x.y*w.y;
            a2x += x.z*w.x; a2y += x.z*w.y;
            a3x += x.w*w.x; a3y += x.w*w.y;
        }
        float bb0=b1[c2], bb1=b1[c2+1];
        float s0=g1[c2]*rsqrtf(v1[c2]+BN_EPS), s1=g1[c2+1]*rsqrtf(v1[c2+1]+BN_EPS);
        float mm0=m1[c2], mm1=m1[c2+1], q0=be1[c2], q1=be1[c2+1];
        float4 o0, o1;
        o0.x=(lrelu(a0x+bb0)-mm0)*s0+q0; o0.y=(lrelu(a1x+bb0)-mm0)*s0+q0;
        o0.z=(lrelu(a2x+bb0)-mm0)*s0+q0; o0.w=(lrelu(a3x+bb0)-mm0)*s0+q0;
        o1.x=(lrelu(a0y+bb1)-mm1)*s1+q1; o1.y=(lrelu(a1y+bb1)-mm1)*s1+q1;
        o1.z=(lrelu(a2y+bb1)-mm1)*s1+q1; o1.w=(lrelu(a3y+bb1)-mm1)*s1+q1;
        *(float4*)&sH1[c2*PAD + r4]     = o0;
        *(float4*)&sH1[(c2+1)*PAD + r4] = o1;
    }
    __syncthreads();

    // ---- GEMM2: [64r x 32k] @ [32k x 32c] + bias + lrelu + BN -> sH2 ----
    {
        float a0x=0,a0y=0,a1x=0,a1y=0,a2x=0,a2y=0,a3x=0,a3y=0;
        #pragma unroll 8
        for (int k = 0; k < 32; ++k) {
            float2 w = *(const float2*)&sW2[k*32 + c2];
            float4 x = *(const float4*)&sH1[k*PAD + r4];
            a0x += x.x*w.x; a0y += x.x*w.y;
            a1x += x.y*w.x; a1y += x.y*w.y;
            a2x += x.z*w.x; a2y += x.z*w.y;
            a3x += x.w*w.x; a3y += x.w*w.y;
        }
        float bb0=b2[c2], bb1=b2[c2+1];
        float s0=g2[c2]*rsqrtf(v2[c2]+BN_EPS), s1=g2[c2+1]*rsqrtf(v2[c2+1]+BN_EPS);
        float mm0=m2[c2], mm1=m2[c2+1], q0=be2[c2], q1=be2[c2+1];
        float4 o0, o1;
        o0.x=(lrelu(a0x+bb0)-mm0)*s0+q0; o0.y=(lrelu(a1x+bb0)-mm0)*s0+q0;
        o0.z=(lrelu(a2x+bb0)-mm0)*s0+q0; o0.w=(lrelu(a3x+bb0)-mm0)*s0+q0;
        o1.x=(lrelu(a0y+bb1)-mm1)*s1+q1; o1.y=(lrelu(a1y+bb1)-mm1)*s1+q1;
        o1.z=(lrelu(a2y+bb1)-mm1)*s1+q1; o1.w=(lrelu(a3y+bb1)-mm1)*s1+q1;
        *(float4*)&sH2[c2*PAD + r4]     = o0;
        *(float4*)&sH2[(c2+1)*PAD + r4] = o1;
    }
    __syncthreads();

    // ---- GEMM3: [64r x 32k] @ [32k x 64c] + bias + lrelu -> sH3 (h^T) ----
    int c4 = 4*tx;
    {
        float acc[4][4] = {};
        #pragma unroll 8
        for (int k = 0; k < 32; ++k) {
            float4 w = *(const float4*)&sW3[k*64 + c4];
            float4 x = *(const float4*)&sH2[k*PAD + r4];
            acc[0][0]+=x.x*w.x; acc[0][1]+=x.x*w.y; acc[0][2]+=x.x*w.z; acc[0][3]+=x.x*w.w;
            acc[1][0]+=x.y*w.x; acc[1][1]+=x.y*w.y; acc[1][2]+=x.y*w.z; acc[1][3]+=x.y*w.w;
            acc[2][0]+=x.z*w.x; acc[2][1]+=x.z*w.y; acc[2][2]+=x.z*w.z; acc[2][3]+=x.z*w.w;
            acc[3][0]+=x.w*w.x; acc[3][1]+=x.w*w.y; acc[3][2]+=x.w*w.z; acc[3][3]+=x.w*w.w;
        }
        float bb0=b3[c4], bb1=b3[c4+1], bb2=b3[c4+2], bb3=b3[c4+3];
        #pragma unroll
        for (int j = 0; j < 4; ++j) {
            float4 o;
            o.x = lrelu(acc[0][j] + ((j==0)?bb0:(j==1)?bb1:(j==2)?bb2:bb3));
            o.y = lrelu(acc[1][j] + ((j==0)?bb0:(j==1)?bb1:(j==2)?bb2:bb3));
            o.z = lrelu(acc[2][j] + ((j==0)?bb0:(j==1)?bb1:(j==2)?bb2:bb3));
            o.w = lrelu(acc[3][j] + ((j==0)?bb0:(j==1)?bb1:(j==2)?bb2:bb3));
            *(float4*)&sH3[(c4+j)*PAD + r4] = o;
        }
    }
    __syncthreads();

    // ---- GEMM4: h2 = h @ Wo1_bot  (no bias/act) -> d_h2 ----
    {
        float acc[4][4] = {};
        #pragma unroll 8
        for (int k = 0; k < 64; ++k) {
            float4 w = *(const float4*)&sWb[k*64 + c4];
            float4 x = *(const float4*)&sH3[k*PAD + r4];
            acc[0][0]+=x.x*w.x; acc[0][1]+=x.x*w.y; acc[0][2]+=x.x*w.z; acc[0][3]+=x.x*w.w;
            acc[1][0]+=x.y*w.x; acc[1][1]+=x.y*w.y; acc[1][2]+=x.y*w.z; acc[1][3]+=x.y*w.w;
            acc[2][0]+=x.z*w.x; acc[2][1]+=x.z*w.y; acc[2][2]+=x.z*w.z; acc[2][3]+=x.z*w.w;
            acc[3][0]+=x.w*w.x; acc[3][1]+=x.w*w.y; acc[3][2]+=x.w*w.z; acc[3][3]+=x.w*w.w;
        }
        #pragma unroll
        for (int i = 0; i < 4; ++i) {
            float4 o; o.x=acc[i][0]; o.y=acc[i][1]; o.z=acc[i][2]; o.w=acc[i][3];
            *(float4*)&d_h2[(size_t)(r0+r4+i)*64 + c4] = o;
        }
    }
}

// ---------------- K4: t_pre = lrelu(feat@Win+bin) @ Wo1_top + bo1 + h2[inv] ------------
// block = 64 points, 256 threads; dynamic smem 67840 B -> 3 CTAs/SM
__global__ void __launch_bounds__(256) k_tpre(
    const float* __restrict__ feat,
    const float* __restrict__ Win, const float* __restrict__ bin,
    const float* __restrict__ Wo1, const float* __restrict__ bo1)
{
    extern __shared__ float sm[];
    float* sWin = sm;               // [64][64]
    float* sWt  = sWin + 4096;      // [64][64] = Wo1 rows 0..63
    float* sA   = sWt  + 4096;      // [64][PAD] feat^T
    float* sI   = sA   + 64*PAD;    // [64][PAD] identity^T
    int*   sInv = (int*)(sI + 64*PAD);  // [64]
    int tid = threadIdx.x;

    for (int i = tid; i < 4096; i += 256) sWin[i] = Win[i];
    for (int i = tid; i < 4096; i += 256) sWt[i]  = Wo1[i];
    int p0 = blockIdx.x * 64;
    if (tid < 64) sInv[tid] = d_inv[p0 + tid];
    for (int idx = tid; idx < 4096; idx += 256) {
        int row = idx >> 6, k = idx & 63;
        sA[k*PAD + row] = feat[(size_t)p0*64 + idx];
    }
    __syncthreads();

    int tx = tid & 15, ty = tid >> 4;
    int c4 = 4*tx, r4 = 4*ty;

    // ---- identity GEMM: 64x64x64 + bias + lrelu -> sI ----
    {
        float acc[4][4] = {};
        #pragma unroll 8
        for (int k = 0; k < 64; ++k) {
            float4 w = *(const float4*)&sWin[k*64 + c4];
            float4 x = *(const float4*)&sA[k*PAD + r4];
            acc[0][0]+=x.x*w.x; acc[0][1]+=x.x*w.y; acc[0][2]+=x.x*w.z; acc[0][3]+=x.x*w.w;
            acc[1][0]+=x.y*w.x; acc[1][1]+=x.y*w.y; acc[1][2]+=x.y*w.z; acc[1][3]+=x.y*w.w;
            acc[2][0]+=x.z*w.x; acc[2][1]+=x.z*w.y; acc[2][2]+=x.z*w.z; acc[2][3]+=x.z*w.w;
            acc[3][0]+=x.w*w.x; acc[3][1]+=x.w*w.y; acc[3][2]+=x.w*w.z; acc[3][3]+=x.w*w.w;
        }
        float bb0=bin[c4], bb1=bin[c4+1], bb2=bin[c4+2], bb3=bin[c4+3];
        #pragma unroll
        for (int j = 0; j < 4; ++j) {
            float bj = (j==0)?bb0:(j==1)?bb1:(j==2)?bb2:bb3;
            float4 o;
            o.x = lrelu(acc[0][j]+bj); o.y = lrelu(acc[1][j]+bj);
            o.z = lrelu(acc[2][j]+bj); o.w = lrelu(acc[3][j]+bj);
            *(float4*)&sI[(c4+j)*PAD + r4] = o;
        }
    }
    __syncthreads();

    // ---- t_pre GEMM: 64x64x64 + bo1 + h2[inv] -> d_tpre ----
    {
        float acc[4][4] = {};
        #pragma unroll 8
        for (int k = 0; k < 64; ++k) {
            float4 w = *(const float4*)&sWt[k*64 + c4];
            float4 x = *(const float4*)&sI[k*PAD + r4];
            acc[0][0]+=x.x*w.x; acc[0][1]+=x.x*w.y; acc[0][2]+=x.x*w.z; acc[0][3]+=x.x*w.w;
            acc[1][0]+=x.y*w.x; acc[1][1]+=x.y*w.y; acc[1][2]+=x.y*w.z; acc[1][3]+=x.y*w.w;
            acc[2][0]+=x.z*w.x; acc[2][1]+=x.z*w.y; acc[2][2]+=x.z*w.z; acc[2][3]+=x.z*w.w;
            acc[3][0]+=x.w*w.x; acc[3][1]+=x.w*w.y; acc[3][2]+=x.w*w.z; acc[3][3]+=x.w*w.w;
        }
        float bb0=bo1[c4], bb1=bo1[c4+1], bb2=bo1[c4+2], bb3=bo1[c4+3];
        #pragma unroll
        for (int i = 0; i < 4; ++i) {
            float4 g = *(const float4*)&d_h2[(size_t)sInv[r4+i]*64 + c4];
            float4 o;
            o.x = acc[i][0]+bb0+g.x; o.y = acc[i][1]+bb1+g.y;
            o.z = acc[i][2]+bb2+g.z; o.w = acc[i][3]+bb3+g.w;
            *(float4*)&d_tpre[(size_t)(p0+r4+i)*64 + c4] = o;
        }
    }
}

// ---------------- K5: gather + lrelu + vector segment reduce ----------------
__global__ void k_scatter(const int* __restrict__ cinv, const int* __restrict__ sinv){
    int t = blockIdx.x*blockDim.x + threadIdx.x;
    if (t >= N_SC*16) return;
    int p = t >> 4, q = t & 15;
    int j = __ldg(&cinv[p]);
    int m = __ldg(&sinv[p]);
    float4 v = *(const float4*)&d_tpre[(size_t)j*64 + q*4];
    v.x = lrelu(v.x); v.y = lrelu(v.y); v.z = lrelu(v.z); v.w = lrelu(v.w);
    red_v4(&d_usum[(size_t)m*64 + q*4], v);
    if (q == 0) atomicAdd(&d_ucnt[m], 1);
}

// ---------------- K6: v_feat = (u_sum/cnt) @ Wo2 + bo2 (0 for empty segs) ----------------
__global__ void __launch_bounds__(256) k_final(
    const float* __restrict__ Wo2, const float* __restrict__ bo2,
    float* __restrict__ out)
{
    __shared__ float sW[64*64];
    __shared__ float sA[64*PAD];
    int tid = threadIdx.x;
    for (int i = tid; i < 4096; i += 256) sW[i] = Wo2[i];
    int m0 = blockIdx.x * 64;
    for (int idx = tid; idx < 4096; idx += 256) {
        int row = idx >> 6, k = idx & 63;
        int m = m0 + row;
        float v = 0.f;
        if (m < M_SEG) {
            int cc = d_ucnt[m];
            v = (cc > 0) ? d_usum[(size_t)m*64 + k] * (1.f/(float)cc) : 0.f;
        }
        sA[k*PAD + row] = v;
    }
    __syncthreads();

    int tx = tid & 15, ty = tid >> 4;
    int c4 = 4*tx, r4 = 4*ty;
    float acc[4][4] = {};
    #pragma unroll 8
    for (int k = 0; k < 64; ++k) {
        float4 w = *(const float4*)&sW[k*64 + c4];
        float4 x = *(const float4*)&sA[k*PAD + r4];
        acc[0][0]+=x.x*w.x; acc[0][1]+=x.x*w.y; acc[0][2]+=x.x*w.z; acc[0][3]+=x.x*w.w;
        acc[1][0]+=x.y*w.x; acc[1][1]+=x.y*w.y; acc[1][2]+=x.y*w.z; acc[1][3]+=x.y*w.w;
        acc[2][0]+=x.z*w.x; acc[2][1]+=x.z*w.y; acc[2][2]+=x.z*w.z; acc[2][3]+=x.z*w.w;
        acc[3][0]+=x.w*w.x; acc[3][1]+=x.w*w.y; acc[3][2]+=x.w*w.z; acc[3][3]+=x.w*w.w;
    }
    float bb0=bo2[c4], bb1=bo2[c4+1], bb2=bo2[c4+2], bb3=bo2[c4+3];
    #pragma unroll
    for (int i = 0; i < 4; ++i) {
        int m = m0 + r4 + i;
        if (m < M_SEG) {
            int cc = d_ucnt[m];
            float4 ov;
            if (cc > 0) { ov.x = acc[i][0]+bb0; ov.y = acc[i][1]+bb1; ov.z = acc[i][2]+bb2; ov.w = acc[i][3]+bb3; }
            else        { ov.x = 0.f; ov.y = 0.f; ov.z = 0.f; ov.w = 0.f; }
            *(float4*)&out[(size_t)m*64 + c4] = ov;
        }
    }
}

// ---------------- launch ----------------
#define SMEM_MLP  (22272*4)   /* 89088 B */
#define SMEM_TPRE (16896*4 + 256)  /* 67840 B */

extern "C" void kernel_launch(void* const* d_in, const int* in_sizes, int n_in,
                              void* d_out, int out_size)
{
    const float* feat  = (const float*)d_in[0];
    const int4*  coors = (const int4*)d_in[1];
    const int*   cinv  = (const int*)d_in[2];
    const int*   sinv  = (const int*)d_in[3];
    const float* Win = (const float*)d_in[4];
    const float* bin = (const float*)d_in[5];
    const float* W1  = (const float*)d_in[6];
    const float* b1  = (const float*)d_in[7];
    const float* g1  = (const float*)d_in[8];
    const float* be1 = (const float*)d_in[9];
    const float* m1  = (const float*)d_in[10];
    const float* v1  = (const float*)d_in[11];
    const float* W2  = (const float*)d_in[12];
    const float* b2  = (const float*)d_in[13];
    const float* g2  = (const float*)d_in[14];
    const float* be2 = (const float*)d_in[15];
    const float* m2  = (const float*)d_in[16];
    const float* v2  = (const float*)d_in[17];
    const float* W3  = (const float*)d_in[18];
    const float* b3  = (const float*)d_in[19];
    const float* Wo1 = (const float*)d_in[20];
    const float* bo1 = (const float*)d_in[21];
    const float* Wo2 = (const float*)d_in[22];
    const float* bo2 = (const float*)d_in[23];
    float* out = (float*)d_out;

    cudaFuncSetAttribute(k_mlp,  cudaFuncAttributeMaxDynamicSharedMemorySize, SMEM_MLP);
    cudaFuncSetAttribute(k_tpre, cudaFuncAttributeMaxDynamicSharedMemorySize, SMEM_TPRE);

    void *p_map, *p_cnt, *p_dsum, *p_usum, *p_ucnt;
    cudaGetSymbolAddress(&p_map,  d_map);
    cudaGetSymbolAddress(&p_cnt,  d_cnt);
    cudaGetSymbolAddress(&p_dsum, d_dsum);
    cudaGetSymbolAddress(&p_usum, d_usum);
    cudaGetSymbolAddress(&p_ucnt, d_ucnt);
    cudaMemsetAsync(p_map,  0xFF, sizeof(int)  * MAPSZ);           // -1
    cudaMemsetAsync(p_cnt,  0,    sizeof(int)  * N_PT);
    cudaMemsetAsync(p_dsum, 0,    sizeof(float)* (size_t)N_PT*64);
    cudaMemsetAsync(p_usum, 0,    sizeof(float)* (size_t)M_SEG*64);
    cudaMemsetAsync(p_ucnt, 0,    sizeof(int)  * M_SEG);

    k_claim  <<<(N_PT + 255)/256, 256>>>(coors);
    k_accum  <<<(N_PT + 255)/256, 256>>>(feat);
    k_mlp    <<<N_PT/64, 256, SMEM_MLP>>>(feat, W1,b1,g1,be1,m1,v1,
                                          W2,b2,g2,be2,m2,v2, W3,b3, Wo1);
    k_tpre   <<<N_PT/64, 256, SMEM_TPRE>>>(feat, Win, bin, Wo1, bo1);
    k_scatter<<<(N_SC*16)/256, 256>>>(cinv, sinv);
    k_final  <<<(M_SEG + 63)/64, 256>>>(Wo2, bo2, out);
}

// round 5
// speedup vs baseline: 1.5687x; 1.3451x over previous
#include <cuda_runtime.h>

#define N_PT   400000
#define N_SC   1000000
#define M_SEG  100000
#define SH_    120
#define MAPSZ  (4*SH_*SH_*SH_)   /* 6,912,000 */
#define BN_EPS 1e-5f
#define PAD    68

typedef unsigned long long u64;

// ---------------- scratch (static __device__, no allocations) ----------------
__device__ int   d_map[MAPSZ];
__device__ int   d_inv[N_PT];
__device__ int   d_cnt[N_PT];
__device__ float d_dsum[(size_t)N_PT*64];
__device__ float d_h2  [(size_t)N_PT*64];   // h @ Wo1_bot (rep rows)
__device__ float d_tpre[(size_t)N_PT*64];
__device__ float d_usum[(size_t)M_SEG*64];
__device__ int   d_ucnt[M_SEG];

__device__ __forceinline__ float lrelu(float x){ return x >= 0.f ? x : 0.1f*x; }

__device__ __forceinline__ u64 pk2(float v){
    u64 r; asm("mov.b64 %0, {%1, %1};" : "=l"(r) : "f"(v)); return r;
}
__device__ __forceinline__ void fma2(u64& d, u64 a, u64 b){
    asm("fma.rn.f32x2 %0, %1, %2, %0;" : "+l"(d) : "l"(a), "l"(b));
}
__device__ __forceinline__ void unpk(u64 v, float& lo, float& hi){
    asm("mov.b64 {%0, %1}, %2;" : "=f"(lo), "=f"(hi) : "l"(v));
}
__device__ __forceinline__ void red_v4(float* p, float4 v){
    asm volatile("red.global.add.v4.f32 [%0], {%1, %2, %3, %4};"
                 :: "l"(p), "f"(v.x), "f"(v.y), "f"(v.z), "f"(v.w) : "memory");
}

// ---------------- K1: voxel-key claim + inverse map + counts ----------------
__global__ void k_claim(const int4* __restrict__ coors){
    int i = blockIdx.x*blockDim.x + threadIdx.x;
    if (i >= N_PT) return;
    int4 c = coors[i];
    int key = ((c.x*SH_ + (c.y>>1))*SH_ + (c.z>>1))*SH_ + (c.w>>1);
    int old = atomicCAS(&d_map[key], -1, i);
    int rep = (old == -1) ? i : old;
    d_inv[i] = rep;
    atomicAdd(&d_cnt[rep], 1);
}

// ---------------- K2: sparse feature accumulate (only multi-member reps) ------------
__global__ void k_accum(const float* __restrict__ feat){
    int i = blockIdx.x*blockDim.x + threadIdx.x;
    if (i >= N_PT) return;
    int rep = d_inv[i];
    if (__ldg(&d_cnt[rep]) > 1) {
        const float4* src = (const float4*)&feat[(size_t)i*64];
        float* dst = &d_dsum[(size_t)rep*64];
        #pragma unroll
        for (int q = 0; q < 16; ++q) red_v4(&dst[4*q], src[q]);
    }
}

// ---------------- K3: rep MLP 64->32->32->64 (+BN,+lrelu) then @Wo1_bot -> d_h2 -------
// 64 rows/CTA, 256 thr, single ping-pong act buffer; smem 54272 B -> 4 CTAs/SM
__global__ void __launch_bounds__(256, 4) k_mlp(
    const float* __restrict__ feat,
    const float* __restrict__ W1, const float* __restrict__ b1,
    const float* __restrict__ g1, const float* __restrict__ be1,
    const float* __restrict__ m1, const float* __restrict__ v1,
    const float* __restrict__ W2, const float* __restrict__ b2,
    const float* __restrict__ g2, const float* __restrict__ be2,
    const float* __restrict__ m2, const float* __restrict__ v2,
    const float* __restrict__ W3, const float* __restrict__ b3,
    const float* __restrict__ Wo1)
{
    extern __shared__ float sm[];
    float* sW1 = sm;               // [64][32]
    float* sW2 = sW1 + 2048;       // [32][32]
    float* sW3 = sW2 + 1024;       // [32][64]
    float* sWb = sW3 + 2048;       // [64][64] = Wo1 rows 64..127
    float* buf = sWb + 4096;       // [64][PAD] act^T ping-pong
    int tid = threadIdx.x;

    for (int i = tid; i < 2048; i += 256) sW1[i] = W1[i];
    for (int i = tid; i < 1024; i += 256) sW2[i] = W2[i];
    for (int i = tid; i < 2048; i += 256) sW3[i] = W3[i];
    for (int i = tid; i < 4096; i += 256) sWb[i] = Wo1[4096 + i];

    int r0 = blockIdx.x * 64;
    for (int idx = tid; idx < 4096; idx += 256) {
        int row = idx >> 6, k = idx & 63;
        int cc = d_cnt[r0 + row];
        float v = (cc > 1) ? d_dsum[(size_t)r0*64 + idx] * (1.f/(float)cc)
                           : feat[(size_t)r0*64 + idx];
        buf[k*PAD + row] = v;
    }
    __syncthreads();

    int tx = tid & 15, ty = tid >> 4;
    int c2 = 2*tx, r4 = 4*ty, c4 = 4*tx;

    // ---- GEMM1: [64r x 64k] @ [64k x 32c], +b1, lrelu, BN1 ----
    {
        u64 a[2][2] = {};
        #pragma unroll 8
        for (int k = 0; k < 64; ++k) {
            ulonglong2 xp = *(const ulonglong2*)&buf[k*PAD + r4];
            float2 w = *(const float2*)&sW1[k*32 + c2];
            u64 w0 = pk2(w.x), w1 = pk2(w.y);
            fma2(a[0][0], xp.x, w0); fma2(a[0][1], xp.x, w1);
            fma2(a[1][0], xp.y, w0); fma2(a[1][1], xp.y, w1);
        }
        float y[2][4];
        #pragma unroll
        for (int j = 0; j < 2; ++j) {
            int c = c2 + j;
            float bb = b1[c], s = g1[c]*rsqrtf(v1[c]+BN_EPS), mm = m1[c], q = be1[c];
            float u0,u1,u2,u3;
            unpk(a[0][j], u0, u1); unpk(a[1][j], u2, u3);
            y[j][0]=(lrelu(u0+bb)-mm)*s+q; y[j][1]=(lrelu(u1+bb)-mm)*s+q;
            y[j][2]=(lrelu(u2+bb)-mm)*s+q; y[j][3]=(lrelu(u3+bb)-mm)*s+q;
        }
        __syncthreads();
        #pragma unroll
        for (int j = 0; j < 2; ++j) {
            *(float2*)&buf[(c2+j)*PAD + r4]     = make_float2(y[j][0], y[j][1]);
            *(float2*)&buf[(c2+j)*PAD + r4 + 2] = make_float2(y[j][2], y[j][3]);
        }
        __syncthreads();
    }

    // ---- GEMM2: [64r x 32k] @ [32k x 32c], +b2, lrelu, BN2 ----
    {
        u64 a[2][2] = {};
        #pragma unroll 8
        for (int k = 0; k < 32; ++k) {
            ulonglong2 xp = *(const ulonglong2*)&buf[k*PAD + r4];
            float2 w = *(const float2*)&sW2[k*32 + c2];
            u64 w0 = pk2(w.x), w1 = pk2(w.y);
            fma2(a[0][0], xp.x, w0); fma2(a[0][1], xp.x, w1);
            fma2(a[1][0], xp.y, w0); fma2(a[1][1], xp.y, w1);
        }
        float y[2][4];
        #pragma unroll
        for (int j = 0; j < 2; ++j) {
            int c = c2 + j;
            float bb = b2[c], s = g2[c]*rsqrtf(v2[c]+BN_EPS), mm = m2[c], q = be2[c];
            float u0,u1,u2,u3;
            unpk(a[0][j], u0, u1); unpk(a[1][j], u2, u3);
            y[j][0]=(lrelu(u0+bb)-mm)*s+q; y[j][1]=(lrelu(u1+bb)-mm)*s+q;
            y[j][2]=(lrelu(u2+bb)-mm)*s+q; y[j][3]=(lrelu(u3+bb)-mm)*s+q;
        }
        __syncthreads();
        #pragma unroll
        for (int j = 0; j < 2; ++j) {
            *(float2*)&buf[(c2+j)*PAD + r4]     = make_float2(y[j][0], y[j][1]);
            *(float2*)&buf[(c2+j)*PAD + r4 + 2] = make_float2(y[j][2], y[j][3]);
        }
        __syncthreads();
    }

    // ---- GEMM3: [64r x 32k] @ [32k x 64c], +b3, lrelu -> h^T ----
    {
        u64 a[2][4] = {};
        #pragma unroll 8
        for (int k = 0; k < 32; ++k) {
            ulonglong2 xp = *(const ulonglong2*)&buf[k*PAD + r4];
            float4 w = *(const float4*)&sW3[k*64 + c4];
            u64 w0 = pk2(w.x), w1 = pk2(w.y), w2 = pk2(w.z), w3 = pk2(w.w);
            fma2(a[0][0], xp.x, w0); fma2(a[0][1], xp.x, w1);
            fma2(a[0][2], xp.x, w2); fma2(a[0][3], xp.x, w3);
            fma2(a[1][0], xp.y, w0); fma2(a[1][1], xp.y, w1);
            fma2(a[1][2], xp.y, w2); fma2(a[1][3], xp.y, w3);
        }
        float y[4][4];
        #pragma unroll
        for (int j = 0; j < 4; ++j) {
            float bb = b3[c4+j];
            float u0,u1,u2,u3;
            unpk(a[0][j], u0, u1); unpk(a[1][j], u2, u3);
            y[j][0]=lrelu(u0+bb); y[j][1]=lrelu(u1+bb);
            y[j][2]=lrelu(u2+bb); y[j][3]=lrelu(u3+bb);
        }
        __syncthreads();
        #pragma unroll
        for (int j = 0; j < 4; ++j) {
            *(float2*)&buf[(c4+j)*PAD + r4]     = make_float2(y[j][0], y[j][1]);
            *(float2*)&buf[(c4+j)*PAD + r4 + 2] = make_float2(y[j][2], y[j][3]);
        }
        __syncthreads();
    }

    // ---- GEMM4: h2 = h @ Wo1_bot -> d_h2 (global) ----
    {
        u64 a[2][4] = {};
        #pragma unroll 8
        for (int k = 0; k < 64; ++k) {
            ulonglong2 xp = *(const ulonglong2*)&buf[k*PAD + r4];
            float4 w = *(const float4*)&sWb[k*64 + c4];
            u64 w0 = pk2(w.x), w1 = pk2(w.y), w2 = pk2(w.z), w3 = pk2(w.w);
            fma2(a[0][0], xp.x, w0); fma2(a[0][1], xp.x, w1);
            fma2(a[0][2], xp.x, w2); fma2(a[0][3], xp.x, w3);
            fma2(a[1][0], xp.y, w0); fma2(a[1][1], xp.y, w1);
            fma2(a[1][2], xp.y, w2); fma2(a[1][3], xp.y, w3);
        }
        float r[4][4];   // [row][col]
        #pragma unroll
        for (int j = 0; j < 4; ++j) {
            unpk(a[0][j], r[0][j], r[1][j]);
            unpk(a[1][j], r[2][j], r[3][j]);
        }
        #pragma unroll
        for (int i = 0; i < 4; ++i)
            *(float4*)&d_h2[(size_t)(r0+r4+i)*64 + c4] =
                make_float4(r[i][0], r[i][1], r[i][2], r[i][3]);
    }
}

// ---------------- K4: t_pre = lrelu(feat@Win+bin) @ Wo1_top + bo1 + h2[inv] ----------
// 64 rows/CTA, 256 thr; smem 50688 B -> 4 CTAs/SM
__global__ void __launch_bounds__(256, 4) k_tpre(
    const float* __restrict__ feat,
    const float* __restrict__ Win, const float* __restrict__ bin,
    const float* __restrict__ Wo1, const float* __restrict__ bo1)
{
    extern __shared__ float sm[];
    float* sWin = sm;               // [64][64]
    float* sWt  = sWin + 4096;      // [64][64] = Wo1 rows 0..63
    float* buf  = sWt  + 4096;      // [64][PAD]
    int*   sInv = (int*)(buf + 64*PAD);
    int tid = threadIdx.x;

    for (int i = tid; i < 4096; i += 256) sWin[i] = Win[i];
    for (int i = tid; i < 4096; i += 256) sWt[i]  = Wo1[i];
    int p0 = blockIdx.x * 64;
    if (tid < 64) sInv[tid] = d_inv[p0 + tid];
    for (int idx = tid; idx < 4096; idx += 256) {
        int row = idx >> 6, k = idx & 63;
        buf[k*PAD + row] = feat[(size_t)p0*64 + idx];
    }
    __syncthreads();

    int tx = tid & 15, ty = tid >> 4;
    int c4 = 4*tx, r4 = 4*ty;

    // ---- identity GEMM: 64x64x64, +bin, lrelu ----
    {
        u64 a[2][4] = {};
        #pragma unroll 8
        for (int k = 0; k < 64; ++k) {
            ulonglong2 xp = *(const ulonglong2*)&buf[k*PAD + r4];
            float4 w = *(const float4*)&sWin[k*64 + c4];
            u64 w0 = pk2(w.x), w1 = pk2(w.y), w2 = pk2(w.z), w3 = pk2(w.w);
            fma2(a[0][0], xp.x, w0); fma2(a[0][1], xp.x, w1);
            fma2(a[0][2], xp.x, w2); fma2(a[0][3], xp.x, w3);
            fma2(a[1][0], xp.y, w0); fma2(a[1][1], xp.y, w1);
            fma2(a[1][2], xp.y, w2); fma2(a[1][3], xp.y, w3);
        }
        float y[4][4];
        #pragma unroll
        for (int j = 0; j < 4; ++j) {
            float bb = bin[c4+j];
            float u0,u1,u2,u3;
            unpk(a[0][j], u0, u1); unpk(a[1][j], u2, u3);
            y[j][0]=lrelu(u0+bb); y[j][1]=lrelu(u1+bb);
            y[j][2]=lrelu(u2+bb); y[j][3]=lrelu(u3+bb);
        }
        __syncthreads();
        #pragma unroll
        for (int j = 0; j < 4; ++j) {
            *(float2*)&buf[(c4+j)*PAD + r4]     = make_float2(y[j][0], y[j][1]);
            *(float2*)&buf[(c4+j)*PAD + r4 + 2] = make_float2(y[j][2], y[j][3]);
        }
        __syncthreads();
    }

    // ---- t_pre GEMM: 64x64x64, +bo1, +h2[inv] -> d_tpre ----
    {
        u64 a[2][4] = {};
        #pragma unroll 8
        for (int k = 0; k < 64; ++k) {
            ulonglong2 xp = *(const ulonglong2*)&buf[k*PAD + r4];
            float4 w = *(const float4*)&sWt[k*64 + c4];
            u64 w0 = pk2(w.x), w1 = pk2(w.y), w2 = pk2(w.z), w3 = pk2(w.w);
            fma2(a[0][0], xp.x, w0); fma2(a[0][1], xp.x, w1);
            fma2(a[0][2], xp.x, w2); fma2(a[0][3], xp.x, w3);
            fma2(a[1][0], xp.y, w0); fma2(a[1][1], xp.y, w1);
            fma2(a[1][2], xp.y, w2); fma2(a[1][3], xp.y, w3);
        }
        float r[4][4];
        #pragma unroll
        for (int j = 0; j < 4; ++j) {
            unpk(a[0][j], r[0][j], r[1][j]);
            unpk(a[1][j], r[2][j], r[3][j]);
        }
        float bb0=bo1[c4], bb1=bo1[c4+1], bb2=bo1[c4+2], bb3=bo1[c4+3];
        #pragma unroll
        for (int i = 0; i < 4; ++i) {
            float4 g = *(const float4*)&d_h2[(size_t)sInv[r4+i]*64 + c4];
            *(float4*)&d_tpre[(size_t)(p0+r4+i)*64 + c4] =
                make_float4(r[i][0]+bb0+g.x, r[i][1]+bb1+g.y,
                            r[i][2]+bb2+g.z, r[i][3]+bb3+g.w);
        }
    }
}

// ---------------- K5: gather + lrelu + vector segment reduce ----------------
__global__ void k_scatter(const int* __restrict__ cinv, const int* __restrict__ sinv){
    int t = blockIdx.x*blockDim.x + threadIdx.x;
    if (t >= N_SC*16) return;
    int p = t >> 4, q = t & 15;
    int j = __ldg(&cinv[p]);
    int m = __ldg(&sinv[p]);
    float4 v = *(const float4*)&d_tpre[(size_t)j*64 + q*4];
    v.x = lrelu(v.x); v.y = lrelu(v.y); v.z = lrelu(v.z); v.w = lrelu(v.w);
    red_v4(&d_usum[(size_t)m*64 + q*4], v);
    if (q == 0) atomicAdd(&d_ucnt[m], 1);
}

// ---------------- K6: v_feat = (u_sum/cnt) @ Wo2 + bo2 ----------------
__global__ void __launch_bounds__(256) k_final(
    const float* __restrict__ Wo2, const float* __restrict__ bo2,
    float* __restrict__ out)
{
    __shared__ float sW[64*64];
    __shared__ float sA[64*PAD];
    int tid = threadIdx.x;
    for (int i = tid; i < 4096; i += 256) sW[i] = Wo2[i];
    int m0 = blockIdx.x * 64;
    for (int idx = tid; idx < 4096; idx += 256) {
        int row = idx >> 6, k = idx & 63;
        int m = m0 + row;
        float v = 0.f;
        if (m < M_SEG) {
            int cc = d_ucnt[m];
            v = (cc > 0) ? d_usum[(size_t)m*64 + k] * (1.f/(float)cc) : 0.f;
        }
        sA[k*PAD + row] = v;
    }
    __syncthreads();

    int tx = tid & 15, ty = tid >> 4;
    int c4 = 4*tx, r4 = 4*ty;
    u64 a[2][4] = {};
    #pragma unroll 8
    for (int k = 0; k < 64; ++k) {
        ulonglong2 xp = *(const ulonglong2*)&sA[k*PAD + r4];
        float4 w = *(const float4*)&sW[k*64 + c4];
        u64 w0 = pk2(w.x), w1 = pk2(w.y), w2 = pk2(w.z), w3 = pk2(w.w);
        fma2(a[0][0], xp.x, w0); fma2(a[0][1], xp.x, w1);
        fma2(a[0][2], xp.x, w2); fma2(a[0][3], xp.x, w3);
        fma2(a[1][0], xp.y, w0); fma2(a[1][1], xp.y, w1);
        fma2(a[1][2], xp.y, w2); fma2(a[1][3], xp.y, w3);
    }
    float r[4][4];
    #pragma unroll
    for (int j = 0; j < 4; ++j) {
        unpk(a[0][j], r[0][j], r[1][j]);
        unpk(a[1][j], r[2][j], r[3][j]);
    }
    float bb0=bo2[c4], bb1=bo2[c4+1], bb2=bo2[c4+2], bb3=bo2[c4+3];
    #pragma unroll
    for (int i = 0; i < 4; ++i) {
        int m = m0 + r4 + i;
        if (m < M_SEG) {
            int cc = d_ucnt[m];
            float4 ov = (cc > 0)
                ? make_float4(r[i][0]+bb0, r[i][1]+bb1, r[i][2]+bb2, r[i][3]+bb3)
                : make_float4(0.f, 0.f, 0.f, 0.f);
            *(float4*)&out[(size_t)m*64 + c4] = ov;
        }
    }
}

// ---------------- launch ----------------
#define SMEM_MLP  ((2048+1024+2048+4096+64*PAD)*4)          /* 54272 B */
#define SMEM_TPRE ((4096+4096+64*PAD)*4 + 256)              /* 50688 B */

extern "C" void kernel_launch(void* const* d_in, const int* in_sizes, int n_in,
                              void* d_out, int out_size)
{
    const float* feat  = (const float*)d_in[0];
    const int4*  coors = (const int4*)d_in[1];
    const int*   cinv  = (const int*)d_in[2];
    const int*   sinv  = (const int*)d_in[3];
    const float* Win = (const float*)d_in[4];
    const float* bin = (const float*)d_in[5];
    const float* W1  = (const float*)d_in[6];
    const float* b1  = (const float*)d_in[7];
    const float* g1  = (const float*)d_in[8];
    const float* be1 = (const float*)d_in[9];
    const float* m1  = (const float*)d_in[10];
    const float* v1  = (const float*)d_in[11];
    const float* W2  = (const float*)d_in[12];
    const float* b2  = (const float*)d_in[13];
    const float* g2  = (const float*)d_in[14];
    const float* be2 = (const float*)d_in[15];
    const float* m2  = (const float*)d_in[16];
    const float* v2  = (const float*)d_in[17];
    const float* W3  = (const float*)d_in[18];
    const float* b3  = (const float*)d_in[19];
    const float* Wo1 = (const float*)d_in[20];
    const float* bo1 = (const float*)d_in[21];
    const float* Wo2 = (const float*)d_in[22];
    const float* bo2 = (const float*)d_in[23];
    float* out = (float*)d_out;

    cudaFuncSetAttribute(k_mlp,  cudaFuncAttributeMaxDynamicSharedMemorySize, SMEM_MLP);
    cudaFuncSetAttribute(k_tpre, cudaFuncAttributeMaxDynamicSharedMemorySize, SMEM_TPRE);

    void *p_map, *p_cnt, *p_dsum, *p_usum, *p_ucnt;
    cudaGetSymbolAddress(&p_map,  d_map);
    cudaGetSymbolAddress(&p_cnt,  d_cnt);
    cudaGetSymbolAddress(&p_dsum, d_dsum);
    cudaGetSymbolAddress(&p_usum, d_usum);
    cudaGetSymbolAddress(&p_ucnt, d_ucnt);
    cudaMemsetAsync(p_map,  0xFF, sizeof(int)  * MAPSZ);
    cudaMemsetAsync(p_cnt,  0,    sizeof(int)  * N_PT);
    cudaMemsetAsync(p_dsum, 0,    sizeof(float)* (size_t)N_PT*64);
    cudaMemsetAsync(p_usum, 0,    sizeof(float)* (size_t)M_SEG*64);
    cudaMemsetAsync(p_ucnt, 0,    sizeof(int)  * M_SEG);

    k_claim  <<<(N_PT + 255)/256, 256>>>(coors);
    k_accum  <<<(N_PT + 255)/256, 256>>>(feat);
    k_mlp    <<<N_PT/64, 256, SMEM_MLP>>>(feat, W1,b1,g1,be1,m1,v1,
                                          W2,b2,g2,be2,m2,v2, W3,b3, Wo1);
    k_tpre   <<<N_PT/64, 256, SMEM_TPRE>>>(feat, Win, bin, Wo1, bo1);
    k_scatter<<<(N_SC*16)/256, 256>>>(cinv, sinv);
    k_final  <<<(M_SEG + 63)/64, 256>>>(Wo2, bo2, out);
}